// round 15
// baseline (speedup 1.0000x reference)
#include <cuda_runtime.h>
#include <cuda_bf16.h>
#include <cuda_fp16.h>
#include <math.h>
#include <cstdint>

// ---------------------------------------------------------------------------
// SparseMoE top-2/8, T=4096, H=2048, I=8192, fp32 in/out.
// tcgen05 fp16 GEMMs, all-bulk-copy mainloop (A pre-gathered+pre-swizzled
// into 16KB tiles; hmid written tiled by GEMM1 epilogue), 256x256 CTA tiles
// using all 512 TMEM cols, 3-deep mbarrier pipeline.
// This round: multi-stream graph fork (wprep branch overlaps router/xtile
// and GEMM1) via event fork-join during capture. Kernels unchanged from R14.
// FFMA2 SIMT fallback for the plain-sm_103 compile pass.
// d_out layout: [out (T*H) | router_logits (T*E)], f32.
// ---------------------------------------------------------------------------

#if defined(__CUDA_ARCH__) && (defined(__CUDA_ARCH_FEAT_SM103_ALL) || \
    defined(__CUDA_ARCH_SPECIFIC__) || defined(__CUDA_ARCH_FAMILY_SPECIFIC__))
#define TC_ON 1
#else
#define TC_ON 0
#endif

#define HDIM 2048
#define IDIM 8192
#define NEXP 8
#define NTOK 4096
#define NPAIR (NTOK * 2)
#define NPAIRP 10240            // padded (expert segments 256-aligned)
#define MT_TOT (NPAIRP / 128)   // 80 row-tiles of 128

// -------------------- device scratch ---------------------------------------
__device__ int   g_count[NEXP];
__device__ int   g_off[NEXP];          // 256-aligned
__device__ int   g_topk_e[NPAIR];
__device__ float g_topk_w[NPAIR];
__device__ int   g_rowtok[NPAIRP];
__device__ float g_roww[NPAIRP];
__device__ int   g_pairpos[NPAIR];
__device__ float g_ypart[(size_t)NPAIRP * HDIM];                  // 84 MB

// A tiles for GEMM1: [mt][kb<32] 16KB pre-swizzled fp16 (permuted x rows)
__device__ unsigned char g_xt[(size_t)MT_TOT * 32 * 16384];       // 42 MB
// hmid tiles (GEMM1 out / GEMM2 A): [mt][kbi<128] 16KB (fallback: fp16 linear)
__device__ unsigned char g_hmid_t[(size_t)84 * 128 * 16384];      // 176 MB
// Pre-swizzled fp16 weight tiles: 16KB per (e, tn, kb).
__device__ unsigned char g_win_t[(size_t)NEXP * 64 * 32 * 16384];   // 256 MB
__device__ unsigned char g_wout_t[(size_t)NEXP * 16 * 128 * 16384]; // 256 MB

// -------------------- generic helpers --------------------------------------
__device__ __forceinline__ uint32_t smem_to_u32(const void* p) {
    uint32_t a;
    asm("{ .reg .u64 t; cvta.to.shared.u64 t, %1; cvt.u32.u64 %0, t; }"
        : "=r"(a) : "l"(p));
    return a;
}
__device__ __forceinline__ unsigned sw128(unsigned off) {
    return off ^ ((off >> 3) & 0x70);
}

// f32x2 packed-FMA helpers (fallback path)
__device__ __forceinline__ unsigned long long pack2(float lo, float hi) {
    unsigned long long r;
    asm("mov.b64 %0, {%1, %2};" : "=l"(r) : "f"(lo), "f"(hi));
    return r;
}
__device__ __forceinline__ void unpack2(unsigned long long v, float &lo, float &hi) {
    asm("mov.b64 {%0, %1}, %2;" : "=f"(lo), "=f"(hi) : "l"(v));
}
__device__ __forceinline__ void ffma2(unsigned long long &c,
                                      unsigned long long a,
                                      unsigned long long b) {
    asm("fma.rn.f32x2 %0, %1, %2, %3;" : "=l"(c) : "l"(a), "l"(b), "l"(c));
}

// -------------------- tcgen05 / async PTX (guarded) ------------------------
#if TC_ON
__device__ __forceinline__ uint32_t elect_one_pred() {
    uint32_t pred;
    asm volatile(
        "{\n\t.reg .pred p;\n\t"
        "elect.sync _|p, 0xFFFFFFFF;\n\t"
        "selp.b32 %0, 1, 0, p;\n\t}"
        : "=r"(pred));
    return pred;
}

#define MBARRIER_INIT(addr, count) \
    asm volatile("mbarrier.init.shared.b64 [%0], %1;" \
                 :: "r"((uint32_t)(addr)), "r"((uint32_t)(count)) : "memory")
#define MBARRIER_EXPECT_TX(addr, tx) \
    asm volatile("mbarrier.arrive.expect_tx.shared.b64 _, [%0], %1;" \
                 :: "r"((uint32_t)(addr)), "r"((uint32_t)(tx)) : "memory")
#define CP_ASYNC_BULK(dst, src, bytes, mbar) \
    asm volatile("cp.async.bulk.shared::cluster.global.mbarrier::complete_tx::bytes " \
                 "[%0], [%1], %2, [%3];" \
                 :: "r"((uint32_t)(dst)), "l"(src), "r"((uint32_t)(bytes)), \
                    "r"((uint32_t)(mbar)) : "memory")

#define MBARRIER_WAIT_PARITY(mbar_smem_addr, phase_parity) do { \
    uint32_t _mbar = (uint32_t)(mbar_smem_addr); \
    uint32_t _parity = (uint32_t)(phase_parity); \
    uint32_t _done; \
    asm volatile( \
        "{\n\t.reg .pred p;\n\t" \
        "mbarrier.try_wait.parity.acquire.cta.shared::cta.b64 p, [%1], %2;\n\t" \
        "selp.b32 %0, 1, 0, p;\n\t}" \
        : "=r"(_done) : "r"(_mbar), "r"(_parity) : "memory"); \
    if (!_done) { \
        asm volatile( \
            "{\n\t.reg .pred P1;\n\t" \
            "WAIT_LOOP_%=:\n\t" \
            "mbarrier.try_wait.parity.acquire.cta.shared::cta.b64 P1, [%0], %1, 0x989680;\n\t" \
            "@P1 bra.uni WAIT_DONE_%=;\n\t" \
            "bra.uni WAIT_LOOP_%=;\n\t" \
            "WAIT_DONE_%=:\n\t}" \
            :: "r"(_mbar), "r"(_parity) : "memory"); \
    } \
} while (0)

#define TCGEN05_ALLOC(smem_result_addr, nCols) \
    asm volatile("tcgen05.alloc.cta_group::1.sync.aligned.shared::cta.b32 [%0], %1;" \
                 :: "r"((uint32_t)(smem_result_addr)), "r"((uint32_t)(nCols)) : "memory")
#define TCGEN05_DEALLOC(tmem_addr, nCols) \
    asm volatile("tcgen05.dealloc.cta_group::1.sync.aligned.b32 %0, %1;" \
                 :: "r"(tmem_addr), "r"((uint32_t)(nCols)))
#define TCGEN05_RELINQUISH() \
    asm volatile("tcgen05.relinquish_alloc_permit.cta_group::1.sync.aligned;")
#define TCGEN05_COMMIT(mbar) \
    asm volatile("tcgen05.commit.cta_group::1.mbarrier::arrive::one.shared::cluster.b64 [%0];" \
                 :: "r"((uint32_t)(mbar)) : "memory")
#define TCGEN05_FENCE_AFTER() \
    asm volatile("tcgen05.fence::after_thread_sync;" ::: "memory")
#define TCGEN05_FENCE_BEFORE() \
    asm volatile("tcgen05.fence::before_thread_sync;" ::: "memory")
#define TCGEN05_WAIT_LD() \
    asm volatile("tcgen05.wait::ld.sync.aligned;" ::: "memory")

#define TCGEN05_LD_32X32B_X32(r, tmem_addr) \
    asm volatile( \
        "tcgen05.ld.sync.aligned.32x32b.x32.b32 " \
        "{%0, %1, %2, %3, %4, %5, %6, %7, " \
        " %8, %9, %10, %11, %12, %13, %14, %15, " \
        " %16, %17, %18, %19, %20, %21, %22, %23, " \
        " %24, %25, %26, %27, %28, %29, %30, %31}, [%32];" \
        : "=r"((r)[0]),  "=r"((r)[1]),  "=r"((r)[2]),  "=r"((r)[3]), \
          "=r"((r)[4]),  "=r"((r)[5]),  "=r"((r)[6]),  "=r"((r)[7]), \
          "=r"((r)[8]),  "=r"((r)[9]),  "=r"((r)[10]), "=r"((r)[11]), \
          "=r"((r)[12]), "=r"((r)[13]), "=r"((r)[14]), "=r"((r)[15]), \
          "=r"((r)[16]), "=r"((r)[17]), "=r"((r)[18]), "=r"((r)[19]), \
          "=r"((r)[20]), "=r"((r)[21]), "=r"((r)[22]), "=r"((r)[23]), \
          "=r"((r)[24]), "=r"((r)[25]), "=r"((r)[26]), "=r"((r)[27]), \
          "=r"((r)[28]), "=r"((r)[29]), "=r"((r)[30]), "=r"((r)[31]) \
        : "r"(tmem_addr))

__device__ __forceinline__ void mma_ss(uint32_t d, uint64_t a, uint64_t b,
                                       uint32_t idesc, bool accum) {
    uint32_t en = accum ? 1u : 0u;
    asm volatile(
        "{\n\t.reg .pred p;\n\t"
        "setp.ne.u32 p, %5, 0;\n\t"
        "tcgen05.mma.cta_group::1.kind::f16 [%0], %1, %2, %3, {%4, %4, %4, %4}, p;\n\t}"
        :: "r"(d), "l"(a), "l"(b), "r"(idesc), "r"(0u), "r"(en)
        : "memory");
}
#endif  // TC_ON

static constexpr uint64_t SMEM_DESC_BASE_SW128 =
    (uint64_t(2) << 61) | (uint64_t(1) << 46) | (uint64_t(64) << 32) | (uint64_t(1) << 16);
#define MAKE_SMEM_DESC(base_addr) \
    (SMEM_DESC_BASE_SW128 | ((uint64_t)((base_addr) >> 4) & 0x3FFF))

// idesc: dtype=F32(1<<4), atype=F16(0), btype=F16(0), N/8<<17, M/16<<24
#define GEMM_IDESC 0x8200010u   // M=128, N=128, fp16 x fp16 -> fp32

// -------------------- SMEM layout ------------------------------------------
// Stage (64KB): A0 | A1 | B0 | B1 (16KB each). 3 stages.
#define NSTG   3
#define STG_SZ 65536
#define SM_STG(s) (1024 + (s) * STG_SZ)
#define SMEM_BYTES (1024 + NSTG * STG_SZ)   // 197632
#define FULLB(s)  (16 + (s) * 16)
#define EMPTYB(s) (24 + (s) * 16)

// -------------------- router ------------------------------------------------
__global__ void router_kernel(const float* __restrict__ x,
                              const float* __restrict__ gw,
                              float* __restrict__ logits_out) {
    int warp = (blockIdx.x * blockDim.x + threadIdx.x) >> 5;
    int lane = threadIdx.x & 31;
    if (warp >= NTOK) return;
    const float* xr = x + (size_t)warp * HDIM;

    float acc[NEXP];
#pragma unroll
    for (int e = 0; e < NEXP; ++e) acc[e] = 0.f;
    for (int h = lane; h < HDIM; h += 32) {
        float xv = xr[h];
        float4 g0 = *(const float4*)(gw + (size_t)h * NEXP);
        float4 g1 = *(const float4*)(gw + (size_t)h * NEXP + 4);
        acc[0] += xv * g0.x; acc[1] += xv * g0.y;
        acc[2] += xv * g0.z; acc[3] += xv * g0.w;
        acc[4] += xv * g1.x; acc[5] += xv * g1.y;
        acc[6] += xv * g1.z; acc[7] += xv * g1.w;
    }
#pragma unroll
    for (int e = 0; e < NEXP; ++e)
#pragma unroll
        for (int o = 16; o > 0; o >>= 1)
            acc[e] += __shfl_xor_sync(0xffffffffu, acc[e], o);

    if (lane == 0) {
        *(float4*)(logits_out + (size_t)warp * NEXP) =
            make_float4(acc[0], acc[1], acc[2], acc[3]);
        *(float4*)(logits_out + (size_t)warp * NEXP + 4) =
            make_float4(acc[4], acc[5], acc[6], acc[7]);
        int i0 = 0;
#pragma unroll
        for (int e = 1; e < NEXP; ++e) if (acc[e] > acc[i0]) i0 = e;
        int i1 = (i0 == 0) ? 1 : 0;
#pragma unroll
        for (int e = 0; e < NEXP; ++e)
            if (e != i0 && acc[e] > acc[i1]) i1 = e;
        float m  = fmaxf(acc[i0], acc[i1]);
        float e0 = expf(acc[i0] - m);
        float e1 = expf(acc[i1] - m);
        float inv = 1.f / (e0 + e1);
        g_topk_e[warp * 2]     = i0;
        g_topk_e[warp * 2 + 1] = i1;
        g_topk_w[warp * 2]     = e0 * inv;
        g_topk_w[warp * 2 + 1] = e1 * inv;
    }
}

// ---------- fused init + count + padded offsets + assign (single block) ----
__global__ void assign_fused_kernel() {
    __shared__ int cnt[NEXP], off[NEXP], cur[NEXP];
    int tid = threadIdx.x;
    if (tid < NEXP) { cnt[tid] = 0; cur[tid] = 0; }
    for (int r = tid; r < NPAIRP; r += blockDim.x) {
        g_rowtok[r] = 0;
        g_roww[r]   = 0.f;
    }
    __syncthreads();
    for (int t = tid; t < NTOK; t += blockDim.x) {
        atomicAdd(&cnt[g_topk_e[t * 2]], 1);
        atomicAdd(&cnt[g_topk_e[t * 2 + 1]], 1);
    }
    __syncthreads();
    if (tid == 0) {
        int s = 0;
#pragma unroll
        for (int e = 0; e < NEXP; ++e) {
            off[e] = s; g_off[e] = s; g_count[e] = cnt[e];
            s += (cnt[e] + 255) & ~255;          // 256-aligned segments
        }
    }
    __syncthreads();
    for (int t = tid; t < NTOK; t += blockDim.x) {
#pragma unroll
        for (int k = 0; k < 2; ++k) {
            int e = g_topk_e[t * 2 + k];
            int slot = atomicAdd(&cur[e], 1);
            int row = off[e] + slot;
            g_rowtok[row] = t;
            g_roww[row]   = g_topk_w[t * 2 + k];
            g_pairpos[t * 2 + k] = row;
        }
    }
}

// ---------- xtile: gather + convert + swizzle x into A tiles ---------------
__global__ void xtile_kernel(const float* __restrict__ x) {
    int mt = blockIdx.x, kb = blockIdx.y;
    int t = threadIdx.x;
    int r = t >> 1, hf = t & 1;
    int tok = g_rowtok[mt * 128 + r];
    const float* s = x + (size_t)tok * HDIM + kb * 64 + hf * 32;
    unsigned char* d = g_xt + ((size_t)mt * 32 + kb) * 16384;

    float v[32];
#pragma unroll
    for (int i = 0; i < 8; ++i)
        *(float4*)&v[4 * i] = *(const float4*)(s + 4 * i);
    unsigned out[16];
#pragma unroll
    for (int p = 0; p < 16; ++p) {
        __half2 hh = __floats2half2_rn(v[2 * p], v[2 * p + 1]);
        out[p] = *(unsigned*)&hh;
    }
#pragma unroll
    for (int q = 0; q < 4; ++q) {
        unsigned so = sw128((unsigned)(r * 128 + hf * 64 + q * 16));
        *(uint4*)(d + so) = ((uint4*)out)[q];
    }
}

// -------------------- prep: weights -> pre-swizzled fp16 tiles -------------
__global__ void wprep_kernel(const float* __restrict__ src,
                             unsigned char* __restrict__ dst,
                             int KB, int ldb) {
    int tn = blockIdx.x, kb = blockIdx.y, e = blockIdx.z;
    int NTN = gridDim.x;
    int t = threadIdx.x;
    int n = t & 127;
    int half = t >> 7;
    const float* s = src + (size_t)e * (size_t)(KB * 64) * ldb
                   + (size_t)(kb * 64 + half * 32) * ldb + (size_t)tn * 128 + n;
    unsigned char* d = dst + ((size_t)(e * NTN + tn) * KB + kb) * 16384;

    float v[32];
#pragma unroll
    for (int k = 0; k < 32; ++k)
        v[k] = s[(size_t)k * ldb];
    unsigned out[16];
#pragma unroll
    for (int p = 0; p < 16; ++p) {
        __half2 hh = __floats2half2_rn(v[2 * p], v[2 * p + 1]);
        out[p] = *(unsigned*)&hh;
    }
#pragma unroll
    for (int q = 0; q < 4; ++q) {
        unsigned so = sw128((unsigned)(n * 128 + half * 64 + q * 16));
        *(uint4*)(d + so) = ((uint4*)out)[q];
    }
}

// -------------------- grouped GEMM (256 rows x 256 cols per CTA) -----------
// MODE 0: hmid tiles = fp16(gelu(xt @ win_tiles)),  K=HDIM  (KT64=32)
// MODE 1: ypart = roww * (hmid tiles @ wout_tiles), K=IDIM  (KT64=128)
template <int MODE, int KT64>
__global__ __launch_bounds__(256, 1)
void gemm_tc(const float* __restrict__ Xraw, const float* __restrict__ Braw) {
    const int e   = blockIdx.x >> 5;
    const int tm  = blockIdx.x & 31;         // 256-row tile index within expert
    const int cnt = g_count[e];
    if (tm * 256 >= cnt) return;
    const int tnp  = blockIdx.y;             // 256-col tile index
    const int row0 = g_off[e] + tm * 256;    // 256-aligned
    const int ldb  = (MODE == 0) ? IDIM : HDIM;
    const int NTN  = (MODE == 0) ? 64 : 16;  // 128-col weight tiles
    const int mt0  = row0 >> 7;

    extern __shared__ char smem[];
    const int tid  = threadIdx.x;
    const int wid  = tid >> 5;
    const int lane = tid & 31;

    const unsigned char* Abase =
        (MODE == 0 ? g_xt : g_hmid_t) + (size_t)mt0 * KT64 * 16384;
    const unsigned char* Bbase =
        (MODE == 0 ? g_win_t : g_wout_t) + (size_t)(e * NTN + tnp * 2) * KT64 * 16384;

#if TC_ON
    uint32_t smem_base = smem_to_u32(smem);
    if (wid == 0) TCGEN05_ALLOC(smem_base, 512);
    if (tid == 0) {
#pragma unroll
        for (int s = 0; s < NSTG; ++s) {
            MBARRIER_INIT(smem_base + FULLB(s), 1);    // expect_tx only
            MBARRIER_INIT(smem_base + EMPTYB(s), 1);   // MMA commit
        }
    }
    __syncthreads();
    uint32_t tmem;
    asm volatile("ld.shared.b32 %0, [%1];" : "=r"(tmem) : "r"(smem_base));

    if (wid == 4) {
        // ---------------- producer: 4 bulk copies per k-block --------------
        if (elect_one_pred()) {
            const unsigned char* a0p = Abase;                           // mt0
            const unsigned char* a1p = Abase + (size_t)KT64 * 16384;    // mt0+1
            const unsigned char* b0p = Bbase;                           // tn0
            const unsigned char* b1p = Bbase + (size_t)KT64 * 16384;    // tn1
            for (int kb = 0; kb < KT64; ++kb) {
                int s = kb % NSTG, w = kb / NSTG;
                MBARRIER_WAIT_PARITY(smem_base + EMPTYB(s), (w + 1) & 1);
                MBARRIER_EXPECT_TX(smem_base + FULLB(s), 65536);
                uint32_t stg = smem_base + SM_STG(s);
                size_t o = (size_t)kb * 16384;
                CP_ASYNC_BULK(stg,         a0p + o, 16384, smem_base + FULLB(s));
                CP_ASYNC_BULK(stg + 16384, a1p + o, 16384, smem_base + FULLB(s));
                CP_ASYNC_BULK(stg + 32768, b0p + o, 16384, smem_base + FULLB(s));
                CP_ASYNC_BULK(stg + 49152, b1p + o, 16384, smem_base + FULLB(s));
            }
        }
    } else if (wid == 5) {
        // ---------------- MMA issuer: 4 quadrants x 4 K-steps --------------
        if (elect_one_pred()) {
            for (int kb = 0; kb < KT64; ++kb) {
                int s = kb % NSTG, w = kb / NSTG;
                MBARRIER_WAIT_PARITY(smem_base + FULLB(s), w & 1);
                asm volatile("fence.proxy.async.shared::cta;" ::: "memory");
                uint64_t S  = MAKE_SMEM_DESC(smem_base + SM_STG(s));
                uint64_t A0 = S, A1 = S + 1024, B0 = S + 2048, B1 = S + 3072;
                bool first = (kb == 0);
#pragma unroll
                for (int st = 0; st < 4; ++st)
                    mma_ss(tmem, A0 + st * 2, B0 + st * 2, GEMM_IDESC, !(first && st == 0));
#pragma unroll
                for (int st = 0; st < 4; ++st)
                    mma_ss(tmem + 128, A1 + st * 2, B0 + st * 2, GEMM_IDESC, !(first && st == 0));
#pragma unroll
                for (int st = 0; st < 4; ++st)
                    mma_ss(tmem + 256, A0 + st * 2, B1 + st * 2, GEMM_IDESC, !(first && st == 0));
#pragma unroll
                for (int st = 0; st < 4; ++st)
                    mma_ss(tmem + 384, A1 + st * 2, B1 + st * 2, GEMM_IDESC, !(first && st == 0));
                TCGEN05_COMMIT(smem_base + EMPTYB(s));
            }
        }
    }
    __syncthreads();

    // ---------------- epilogue: warps 0-3, 4 quadrants ---------------------
    if (wid < 4) {
        MBARRIER_WAIT_PARITY(smem_base + EMPTYB((KT64 - 1) % NSTG),
                             ((KT64 - 1) / NSTG) & 1);
        TCGEN05_FENCE_AFTER();
#pragma unroll
        for (int np = 0; np < 2; ++np) {
#pragma unroll
            for (int sub = 0; sub < 2; ++sub) {
                int rloc = wid * 32 + lane;            // row within 128-tile
                int m = sub * 128 + rloc;
                int grow = row0 + m;
                bool valid = (tm * 256 + m) < cnt;
                float wscale = 1.f;
                if (MODE == 1) wscale = valid ? g_roww[grow] : 0.f;
#pragma unroll
                for (int nb = 0; nb < 4; ++nb) {
                    uint32_t dr[32];
                    TCGEN05_LD_32X32B_X32(dr, tmem + np * 256 + sub * 128 + nb * 32);
                    TCGEN05_WAIT_LD();
                    float f[32];
#pragma unroll
                    for (int j = 0; j < 32; ++j) f[j] = __uint_as_float(dr[j]);
                    if (MODE == 0) {
#pragma unroll
                        for (int j = 0; j < 32; ++j) {
                            float t = f[j];
                            f[j] = 0.5f * t * (1.0f + erff(t * 0.7071067811865476f));
                        }
                        unsigned oh[16];
#pragma unroll
                        for (int p = 0; p < 16; ++p) {
                            __half2 hh = __floats2half2_rn(f[2 * p], f[2 * p + 1]);
                            oh[p] = *(unsigned*)&hh;
                        }
                        int c0 = (tnp * 2 + np) * 128 + nb * 32;   // global col
                        int kbi = c0 >> 6, hf = (c0 >> 5) & 1;
                        unsigned char* d = g_hmid_t
                            + ((size_t)(mt0 + sub) * 128 + kbi) * 16384;
#pragma unroll
                        for (int q = 0; q < 4; ++q) {
                            unsigned so = sw128((unsigned)(rloc * 128 + hf * 64 + q * 16));
                            *(uint4*)(d + so) = ((uint4*)oh)[q];
                        }
                    } else if (valid) {
#pragma unroll
                        for (int j = 0; j < 32; ++j) f[j] *= wscale;
                        float* dst = g_ypart + (size_t)grow * HDIM
                                   + (size_t)(tnp * 2 + np) * 128 + nb * 32;
#pragma unroll
                        for (int q = 0; q < 8; ++q)
                            *(float4*)(dst + 4 * q) =
                                make_float4(f[4 * q], f[4 * q + 1], f[4 * q + 2], f[4 * q + 3]);
                    }
                }
            }
        }
        TCGEN05_FENCE_BEFORE();
    }
    __syncthreads();
    if (wid == 0) {
        TCGEN05_RELINQUISH();
        TCGEN05_DEALLOC(tmem, 512);
    }

#else
    // ================= FFMA2 SIMT fallback (compiles on plain sm_103) ======
    (void)lane; (void)wid; (void)Abase; (void)Bbase;
    const int lda = (MODE == 0) ? HDIM : IDIM;
    const int KT16 = KT64 * 4;
    float* As = (float*)smem;
    float* Bs = As + 2 * 16 * 128;
    __half* hmidL = (__half*)g_hmid_t;

    for (int sub = 0; sub < 2; ++sub) {
        for (int np = 0; np < 2; ++np) {
            int mbase = tm * 256 + sub * 128;
            if (mbase >= cnt) break;
            int rowb = row0 + sub * 128;
            int tn = tnp * 2 + np;
            __syncthreads();

            const int am  = tid & 127;
            const int akq = (tid >> 7) << 3;
            const bool avalid = (mbase + am) < cnt;
            int arow_idx = avalid ? (rowb + am) : row0;
            const float* AxRow = Xraw + (size_t)g_rowtok[arow_idx] * HDIM + akq;
            const __half* AhRow = hmidL + (size_t)arow_idx * lda + akq;

            const float* Bb = Braw + (size_t)e * (size_t)KT64 * 64 * ldb + (size_t)tn * 128;
            const int bk = tid >> 4;
            const int bn = (tid & 15) << 3;
            const float* Bp = Bb + (size_t)bk * ldb + bn;
            const int m0 = (tid >> 4) << 3;
            const int n0 = (tid & 15) << 3;

            unsigned long long acc[8][4];
#pragma unroll
            for (int i = 0; i < 8; ++i)
#pragma unroll
                for (int j = 0; j < 4; ++j) acc[i][j] = 0ull;

            auto loadA8 = [&](int k0, float* out8) {
                if (MODE == 0) {
                    float4 a = *(const float4*)(AxRow + k0);
                    float4 b = *(const float4*)(AxRow + k0 + 4);
                    out8[0] = a.x; out8[1] = a.y; out8[2] = a.z; out8[3] = a.w;
                    out8[4] = b.x; out8[5] = b.y; out8[6] = b.z; out8[7] = b.w;
                } else {
                    uint4 h = *(const uint4*)(AhRow + k0);
                    const __half2* hp = (const __half2*)&h;
#pragma unroll
                    for (int p = 0; p < 4; ++p) {
                        float2 hf = __half22float2(hp[p]);
                        out8[2 * p] = hf.x;
                        out8[2 * p + 1] = hf.y;
                    }
                }
            };

            {
                float a8[8];
                loadA8(0, a8);
#pragma unroll
                for (int q = 0; q < 8; ++q) As[(akq + q) * 128 + am] = a8[q];
                *(float4*)&Bs[bk * 128 + bn]     = *(const float4*)(Bp);
                *(float4*)&Bs[bk * 128 + bn + 4] = *(const float4*)(Bp + 4);
            }
            __syncthreads();

            int buf = 0;
            for (int kt = 0; kt < KT16; ++kt) {
                float na8[8]; float4 nb0, nb1;
                if (kt + 1 < KT16) {
                    int k0 = (kt + 1) * 16;
                    loadA8(k0, na8);
                    nb0 = *(const float4*)(Bp + (size_t)k0 * ldb);
                    nb1 = *(const float4*)(Bp + (size_t)k0 * ldb + 4);
                }
                const float* Ab = As + buf * 16 * 128;
                const float* Bbs = Bs + buf * 16 * 128;
#pragma unroll
                for (int kk = 0; kk < 16; ++kk) {
                    float a8[8];
                    *(float4*)&a8[0] = *(const float4*)&Ab[kk * 128 + m0];
                    *(float4*)&a8[4] = *(const float4*)&Ab[kk * 128 + m0 + 4];
                    ulonglong2 bb0 = *(const ulonglong2*)&Bbs[kk * 128 + n0];
                    ulonglong2 bb1 = *(const ulonglong2*)&Bbs[kk * 128 + n0 + 4];
                    unsigned long long b2[4] = {bb0.x, bb0.y, bb1.x, bb1.y};
#pragma unroll
                    for (int i = 0; i < 8; ++i) {
                        unsigned long long a2 = pack2(a8[i], a8[i]);
#pragma unroll
                        for (int j = 0; j < 4; ++j) ffma2(acc[i][j], a2, b2[j]);
                    }
                }
                if (kt + 1 < KT16) {
                    int nb2 = buf ^ 1;
                    float* An = As + nb2 * 16 * 128;
#pragma unroll
                    for (int q = 0; q < 8; ++q) An[(akq + q) * 128 + am] = na8[q];
                    float* Bn = Bs + nb2 * 16 * 128;
                    *(float4*)&Bn[bk * 128 + bn]     = nb0;
                    *(float4*)&Bn[bk * 128 + bn + 4] = nb1;
                    __syncthreads();
                    buf = nb2;
                }
            }

#pragma unroll
            for (int i = 0; i < 8; ++i) {
                int r = mbase + m0 + i;
                if (r < cnt) {
                    int grow = rowb + m0 + i;
                    float v[8];
#pragma unroll
                    for (int j = 0; j < 4; ++j) unpack2(acc[i][j], v[2 * j], v[2 * j + 1]);
                    if (MODE == 0) {
#pragma unroll
                        for (int k = 0; k < 8; ++k) {
                            float t = v[k];
                            v[k] = 0.5f * t * (1.0f + erff(t * 0.7071067811865476f));
                        }
                        size_t off = (size_t)grow * IDIM + (size_t)tn * 128 + n0;
#pragma unroll
                        for (int p = 0; p < 4; ++p) {
                            __half2 hh = __floats2half2_rn(v[2 * p], v[2 * p + 1]);
                            *(unsigned*)(hmidL + off + 2 * p) = *(unsigned*)&hh;
                        }
                    } else {
                        float w = g_roww[grow];
#pragma unroll
                        for (int k = 0; k < 8; ++k) v[k] *= w;
                        float* dst = g_ypart + (size_t)grow * HDIM + (size_t)tn * 128 + n0;
                        *(float4*)(dst)     = make_float4(v[0], v[1], v[2], v[3]);
                        *(float4*)(dst + 4) = make_float4(v[4], v[5], v[6], v[7]);
                    }
                }
            }
            __syncthreads();
        }
    }
#endif  // TC_ON
}

// -------------------- combine ----------------------------------------------
__global__ void combine_kernel(const float* __restrict__ bias,
                               float* __restrict__ out) {
    int idx = blockIdx.x * blockDim.x + threadIdx.x;
    if (idx >= NTOK * (HDIM / 4)) return;
    int t  = idx >> 9;
    int c4 = (idx & 511) << 2;
    int p0 = g_pairpos[t * 2];
    int p1 = g_pairpos[t * 2 + 1];
    float4 bv = *(const float4*)(bias + c4);
    float4 y0 = *(const float4*)(g_ypart + (size_t)p0 * HDIM + c4);
    float4 y1 = *(const float4*)(g_ypart + (size_t)p1 * HDIM + c4);
    float4 o;
    o.x = bv.x + y0.x + y1.x;
    o.y = bv.y + y0.y + y1.y;
    o.z = bv.z + y0.z + y1.z;
    o.w = bv.w + y0.w + y1.w;
    *(float4*)(out + (size_t)t * HDIM + c4) = o;
}

// ---------------------------------------------------------------------------
extern "C" void kernel_launch(void* const* d_in, const int* in_sizes, int n_in,
                              void* d_out, int out_size) {
    const float* x     = (const float*)d_in[0];
    const float* gw    = (const float*)d_in[1];
    const float* w_in  = (const float*)d_in[2];
    const float* w_out = (const float*)d_in[3];
    const float* bias  = (const float*)d_in[4];
    (void)in_sizes; (void)n_in; (void)out_size;

    float* out    = (float*)d_out;
    float* logits = out + (size_t)NTOK * HDIM;

    unsigned char* win_t;
    unsigned char* wout_t;
    cudaGetSymbolAddress((void**)&win_t, g_win_t);
    cudaGetSymbolAddress((void**)&wout_t, g_wout_t);

    cudaFuncSetAttribute(gemm_tc<0, HDIM / 64>,
                         cudaFuncAttributeMaxDynamicSharedMemorySize, SMEM_BYTES);
    cudaFuncSetAttribute(gemm_tc<1, IDIM / 64>,
                         cudaFuncAttributeMaxDynamicSharedMemorySize, SMEM_BYTES);

    // ---- fork: weight-prep branch on a side stream (graph-capture fork) ----
    // Streams/events are host objects (no device memory); created per call and
    // intentionally leaked (kernel_launch only runs for correctness + capture).
    cudaStream_t s1 = 0;
    cudaEvent_t evF = 0, evW1 = 0, evW2 = 0;
    bool forked =
        (cudaStreamCreateWithFlags(&s1, cudaStreamNonBlocking) == cudaSuccess) &&
        (cudaEventCreateWithFlags(&evF,  cudaEventDisableTiming) == cudaSuccess) &&
        (cudaEventCreateWithFlags(&evW1, cudaEventDisableTiming) == cudaSuccess) &&
        (cudaEventCreateWithFlags(&evW2, cudaEventDisableTiming) == cudaSuccess);

    if (forked) {
        cudaEventRecord(evF, 0);
        cudaStreamWaitEvent(s1, evF, 0);
        wprep_kernel<<<dim3(64, 32, NEXP), 256, 0, s1>>>(w_in, win_t, 32, IDIM);
        cudaEventRecord(evW1, s1);
        wprep_kernel<<<dim3(16, 128, NEXP), 256, 0, s1>>>(w_out, wout_t, 128, HDIM);
        cudaEventRecord(evW2, s1);
    }

    router_kernel<<<NTOK / 8, 256>>>(x, gw, logits);
    assign_fused_kernel<<<1, 1024>>>();
    xtile_kernel<<<dim3(MT_TOT, 32), 256>>>(x);

    if (forked) {
        cudaStreamWaitEvent(0, evW1, 0);   // GEMM1 needs win_t
    } else {
        wprep_kernel<<<dim3(64, 32, NEXP), 256>>>(w_in, win_t, 32, IDIM);
    }
    gemm_tc<0, HDIM / 64><<<dim3(NEXP * 32, 32), 256, SMEM_BYTES>>>(x, w_in);

    if (forked) {
        cudaStreamWaitEvent(0, evW2, 0);   // GEMM2 needs wout_t
    } else {
        wprep_kernel<<<dim3(16, 128, NEXP), 256>>>(w_out, wout_t, 128, HDIM);
    }
    gemm_tc<1, IDIM / 64><<<dim3(NEXP * 32, 8), 256, SMEM_BYTES>>>(x, w_out);

    combine_kernel<<<(NTOK * (HDIM / 4)) / 256, 256>>>(bias, out);
}

// round 16
// speedup vs baseline: 1.5524x; 1.5524x over previous
#include <cuda_runtime.h>
#include <cuda_bf16.h>
#include <cuda_fp16.h>
#include <math.h>
#include <cstdint>

// ---------------------------------------------------------------------------
// SparseMoE top-2/8, T=4096, H=2048, I=8192, fp32 in/out.
// tcgen05 fp16 GEMMs, all-bulk-copy mainloop, 256x256 CTA tiles (512 TMEM
// cols), 3-deep mbarrier pipeline. This round: serial launches (fork of R15
// reverted — it contended with the 1-CTA/SM GEMMs) + 16x8 supertile grid
// swizzle so each wave reuses both A and B tiles from L2 (saves ~1.4 GB DRAM).
// FFMA2 SIMT fallback for the plain-sm_103 compile pass.
// d_out layout: [out (T*H) | router_logits (T*E)], f32.
// ---------------------------------------------------------------------------

#if defined(__CUDA_ARCH__) && (defined(__CUDA_ARCH_FEAT_SM103_ALL) || \
    defined(__CUDA_ARCH_SPECIFIC__) || defined(__CUDA_ARCH_FAMILY_SPECIFIC__))
#define TC_ON 1
#else
#define TC_ON 0
#endif

#define HDIM 2048
#define IDIM 8192
#define NEXP 8
#define NTOK 4096
#define NPAIR (NTOK * 2)
#define NPAIRP 10240            // padded (expert segments 256-aligned)
#define MT_TOT (NPAIRP / 128)   // 80 row-tiles of 128

// -------------------- device scratch ---------------------------------------
__device__ int   g_count[NEXP];
__device__ int   g_off[NEXP];          // 256-aligned
__device__ int   g_topk_e[NPAIR];
__device__ float g_topk_w[NPAIR];
__device__ int   g_rowtok[NPAIRP];
__device__ float g_roww[NPAIRP];
__device__ int   g_pairpos[NPAIR];
__device__ float g_ypart[(size_t)NPAIRP * HDIM];                  // 84 MB

// A tiles for GEMM1: [mt][kb<32] 16KB pre-swizzled fp16 (permuted x rows)
__device__ unsigned char g_xt[(size_t)MT_TOT * 32 * 16384];       // 42 MB
// hmid tiles (GEMM1 out / GEMM2 A): [mt][kbi<128] 16KB (fallback: fp16 linear)
__device__ unsigned char g_hmid_t[(size_t)84 * 128 * 16384];      // 176 MB
// Pre-swizzled fp16 weight tiles: 16KB per (e, tn, kb).
__device__ unsigned char g_win_t[(size_t)NEXP * 64 * 32 * 16384];   // 256 MB
__device__ unsigned char g_wout_t[(size_t)NEXP * 16 * 128 * 16384]; // 256 MB

// -------------------- generic helpers --------------------------------------
__device__ __forceinline__ uint32_t smem_to_u32(const void* p) {
    uint32_t a;
    asm("{ .reg .u64 t; cvta.to.shared.u64 t, %1; cvt.u32.u64 %0, t; }"
        : "=r"(a) : "l"(p));
    return a;
}
__device__ __forceinline__ unsigned sw128(unsigned off) {
    return off ^ ((off >> 3) & 0x70);
}

// f32x2 packed-FMA helpers (fallback path)
__device__ __forceinline__ unsigned long long pack2(float lo, float hi) {
    unsigned long long r;
    asm("mov.b64 %0, {%1, %2};" : "=l"(r) : "f"(lo), "f"(hi));
    return r;
}
__device__ __forceinline__ void unpack2(unsigned long long v, float &lo, float &hi) {
    asm("mov.b64 {%0, %1}, %2;" : "=f"(lo), "=f"(hi) : "l"(v));
}
__device__ __forceinline__ void ffma2(unsigned long long &c,
                                      unsigned long long a,
                                      unsigned long long b) {
    asm("fma.rn.f32x2 %0, %1, %2, %3;" : "=l"(c) : "l"(a), "l"(b), "l"(c));
}

// -------------------- tcgen05 / async PTX (guarded) ------------------------
#if TC_ON
__device__ __forceinline__ uint32_t elect_one_pred() {
    uint32_t pred;
    asm volatile(
        "{\n\t.reg .pred p;\n\t"
        "elect.sync _|p, 0xFFFFFFFF;\n\t"
        "selp.b32 %0, 1, 0, p;\n\t}"
        : "=r"(pred));
    return pred;
}

#define MBARRIER_INIT(addr, count) \
    asm volatile("mbarrier.init.shared.b64 [%0], %1;" \
                 :: "r"((uint32_t)(addr)), "r"((uint32_t)(count)) : "memory")
#define MBARRIER_EXPECT_TX(addr, tx) \
    asm volatile("mbarrier.arrive.expect_tx.shared.b64 _, [%0], %1;" \
                 :: "r"((uint32_t)(addr)), "r"((uint32_t)(tx)) : "memory")
#define CP_ASYNC_BULK(dst, src, bytes, mbar) \
    asm volatile("cp.async.bulk.shared::cluster.global.mbarrier::complete_tx::bytes " \
                 "[%0], [%1], %2, [%3];" \
                 :: "r"((uint32_t)(dst)), "l"(src), "r"((uint32_t)(bytes)), \
                    "r"((uint32_t)(mbar)) : "memory")

#define MBARRIER_WAIT_PARITY(mbar_smem_addr, phase_parity) do { \
    uint32_t _mbar = (uint32_t)(mbar_smem_addr); \
    uint32_t _parity = (uint32_t)(phase_parity); \
    uint32_t _done; \
    asm volatile( \
        "{\n\t.reg .pred p;\n\t" \
        "mbarrier.try_wait.parity.acquire.cta.shared::cta.b64 p, [%1], %2;\n\t" \
        "selp.b32 %0, 1, 0, p;\n\t}" \
        : "=r"(_done) : "r"(_mbar), "r"(_parity) : "memory"); \
    if (!_done) { \
        asm volatile( \
            "{\n\t.reg .pred P1;\n\t" \
            "WAIT_LOOP_%=:\n\t" \
            "mbarrier.try_wait.parity.acquire.cta.shared::cta.b64 P1, [%0], %1, 0x989680;\n\t" \
            "@P1 bra.uni WAIT_DONE_%=;\n\t" \
            "bra.uni WAIT_LOOP_%=;\n\t" \
            "WAIT_DONE_%=:\n\t}" \
            :: "r"(_mbar), "r"(_parity) : "memory"); \
    } \
} while (0)

#define TCGEN05_ALLOC(smem_result_addr, nCols) \
    asm volatile("tcgen05.alloc.cta_group::1.sync.aligned.shared::cta.b32 [%0], %1;" \
                 :: "r"((uint32_t)(smem_result_addr)), "r"((uint32_t)(nCols)) : "memory")
#define TCGEN05_DEALLOC(tmem_addr, nCols) \
    asm volatile("tcgen05.dealloc.cta_group::1.sync.aligned.b32 %0, %1;" \
                 :: "r"(tmem_addr), "r"((uint32_t)(nCols)))
#define TCGEN05_RELINQUISH() \
    asm volatile("tcgen05.relinquish_alloc_permit.cta_group::1.sync.aligned;")
#define TCGEN05_COMMIT(mbar) \
    asm volatile("tcgen05.commit.cta_group::1.mbarrier::arrive::one.shared::cluster.b64 [%0];" \
                 :: "r"((uint32_t)(mbar)) : "memory")
#define TCGEN05_FENCE_AFTER() \
    asm volatile("tcgen05.fence::after_thread_sync;" ::: "memory")
#define TCGEN05_FENCE_BEFORE() \
    asm volatile("tcgen05.fence::before_thread_sync;" ::: "memory")
#define TCGEN05_WAIT_LD() \
    asm volatile("tcgen05.wait::ld.sync.aligned;" ::: "memory")

#define TCGEN05_LD_32X32B_X32(r, tmem_addr) \
    asm volatile( \
        "tcgen05.ld.sync.aligned.32x32b.x32.b32 " \
        "{%0, %1, %2, %3, %4, %5, %6, %7, " \
        " %8, %9, %10, %11, %12, %13, %14, %15, " \
        " %16, %17, %18, %19, %20, %21, %22, %23, " \
        " %24, %25, %26, %27, %28, %29, %30, %31}, [%32];" \
        : "=r"((r)[0]),  "=r"((r)[1]),  "=r"((r)[2]),  "=r"((r)[3]), \
          "=r"((r)[4]),  "=r"((r)[5]),  "=r"((r)[6]),  "=r"((r)[7]), \
          "=r"((r)[8]),  "=r"((r)[9]),  "=r"((r)[10]), "=r"((r)[11]), \
          "=r"((r)[12]), "=r"((r)[13]), "=r"((r)[14]), "=r"((r)[15]), \
          "=r"((r)[16]), "=r"((r)[17]), "=r"((r)[18]), "=r"((r)[19]), \
          "=r"((r)[20]), "=r"((r)[21]), "=r"((r)[22]), "=r"((r)[23]), \
          "=r"((r)[24]), "=r"((r)[25]), "=r"((r)[26]), "=r"((r)[27]), \
          "=r"((r)[28]), "=r"((r)[29]), "=r"((r)[30]), "=r"((r)[31]) \
        : "r"(tmem_addr))

__device__ __forceinline__ void mma_ss(uint32_t d, uint64_t a, uint64_t b,
                                       uint32_t idesc, bool accum) {
    uint32_t en = accum ? 1u : 0u;
    asm volatile(
        "{\n\t.reg .pred p;\n\t"
        "setp.ne.u32 p, %5, 0;\n\t"
        "tcgen05.mma.cta_group::1.kind::f16 [%0], %1, %2, %3, {%4, %4, %4, %4}, p;\n\t}"
        :: "r"(d), "l"(a), "l"(b), "r"(idesc), "r"(0u), "r"(en)
        : "memory");
}
#endif  // TC_ON

static constexpr uint64_t SMEM_DESC_BASE_SW128 =
    (uint64_t(2) << 61) | (uint64_t(1) << 46) | (uint64_t(64) << 32) | (uint64_t(1) << 16);
#define MAKE_SMEM_DESC(base_addr) \
    (SMEM_DESC_BASE_SW128 | ((uint64_t)((base_addr) >> 4) & 0x3FFF))

// idesc: dtype=F32(1<<4), atype=F16(0), btype=F16(0), N/8<<17, M/16<<24
#define GEMM_IDESC 0x8200010u   // M=128, N=128, fp16 x fp16 -> fp32

// -------------------- SMEM layout ------------------------------------------
// Stage (64KB): A0 | A1 | B0 | B1 (16KB each). 3 stages.
#define NSTG   3
#define STG_SZ 65536
#define SM_STG(s) (1024 + (s) * STG_SZ)
#define SMEM_BYTES (1024 + NSTG * STG_SZ)   // 197632
#define FULLB(s)  (16 + (s) * 16)
#define EMPTYB(s) (24 + (s) * 16)

// -------------------- router ------------------------------------------------
__global__ void router_kernel(const float* __restrict__ x,
                              const float* __restrict__ gw,
                              float* __restrict__ logits_out) {
    int warp = (blockIdx.x * blockDim.x + threadIdx.x) >> 5;
    int lane = threadIdx.x & 31;
    if (warp >= NTOK) return;
    const float* xr = x + (size_t)warp * HDIM;

    float acc[NEXP];
#pragma unroll
    for (int e = 0; e < NEXP; ++e) acc[e] = 0.f;
    for (int h = lane; h < HDIM; h += 32) {
        float xv = xr[h];
        float4 g0 = *(const float4*)(gw + (size_t)h * NEXP);
        float4 g1 = *(const float4*)(gw + (size_t)h * NEXP + 4);
        acc[0] += xv * g0.x; acc[1] += xv * g0.y;
        acc[2] += xv * g0.z; acc[3] += xv * g0.w;
        acc[4] += xv * g1.x; acc[5] += xv * g1.y;
        acc[6] += xv * g1.z; acc[7] += xv * g1.w;
    }
#pragma unroll
    for (int e = 0; e < NEXP; ++e)
#pragma unroll
        for (int o = 16; o > 0; o >>= 1)
            acc[e] += __shfl_xor_sync(0xffffffffu, acc[e], o);

    if (lane == 0) {
        *(float4*)(logits_out + (size_t)warp * NEXP) =
            make_float4(acc[0], acc[1], acc[2], acc[3]);
        *(float4*)(logits_out + (size_t)warp * NEXP + 4) =
            make_float4(acc[4], acc[5], acc[6], acc[7]);
        int i0 = 0;
#pragma unroll
        for (int e = 1; e < NEXP; ++e) if (acc[e] > acc[i0]) i0 = e;
        int i1 = (i0 == 0) ? 1 : 0;
#pragma unroll
        for (int e = 0; e < NEXP; ++e)
            if (e != i0 && acc[e] > acc[i1]) i1 = e;
        float m  = fmaxf(acc[i0], acc[i1]);
        float e0 = expf(acc[i0] - m);
        float e1 = expf(acc[i1] - m);
        float inv = 1.f / (e0 + e1);
        g_topk_e[warp * 2]     = i0;
        g_topk_e[warp * 2 + 1] = i1;
        g_topk_w[warp * 2]     = e0 * inv;
        g_topk_w[warp * 2 + 1] = e1 * inv;
    }
}

// ---------- fused init + count + padded offsets + assign (single block) ----
__global__ void assign_fused_kernel() {
    __shared__ int cnt[NEXP], off[NEXP], cur[NEXP];
    int tid = threadIdx.x;
    if (tid < NEXP) { cnt[tid] = 0; cur[tid] = 0; }
    for (int r = tid; r < NPAIRP; r += blockDim.x) {
        g_rowtok[r] = 0;
        g_roww[r]   = 0.f;
    }
    __syncthreads();
    for (int t = tid; t < NTOK; t += blockDim.x) {
        atomicAdd(&cnt[g_topk_e[t * 2]], 1);
        atomicAdd(&cnt[g_topk_e[t * 2 + 1]], 1);
    }
    __syncthreads();
    if (tid == 0) {
        int s = 0;
#pragma unroll
        for (int e = 0; e < NEXP; ++e) {
            off[e] = s; g_off[e] = s; g_count[e] = cnt[e];
            s += (cnt[e] + 255) & ~255;          // 256-aligned segments
        }
    }
    __syncthreads();
    for (int t = tid; t < NTOK; t += blockDim.x) {
#pragma unroll
        for (int k = 0; k < 2; ++k) {
            int e = g_topk_e[t * 2 + k];
            int slot = atomicAdd(&cur[e], 1);
            int row = off[e] + slot;
            g_rowtok[row] = t;
            g_roww[row]   = g_topk_w[t * 2 + k];
            g_pairpos[t * 2 + k] = row;
        }
    }
}

// ---------- xtile: gather + convert + swizzle x into A tiles ---------------
__global__ void xtile_kernel(const float* __restrict__ x) {
    int mt = blockIdx.x, kb = blockIdx.y;
    int t = threadIdx.x;
    int r = t >> 1, hf = t & 1;
    int tok = g_rowtok[mt * 128 + r];
    const float* s = x + (size_t)tok * HDIM + kb * 64 + hf * 32;
    unsigned char* d = g_xt + ((size_t)mt * 32 + kb) * 16384;

    float v[32];
#pragma unroll
    for (int i = 0; i < 8; ++i)
        *(float4*)&v[4 * i] = *(const float4*)(s + 4 * i);
    unsigned out[16];
#pragma unroll
    for (int p = 0; p < 16; ++p) {
        __half2 hh = __floats2half2_rn(v[2 * p], v[2 * p + 1]);
        out[p] = *(unsigned*)&hh;
    }
#pragma unroll
    for (int q = 0; q < 4; ++q) {
        unsigned so = sw128((unsigned)(r * 128 + hf * 64 + q * 16));
        *(uint4*)(d + so) = ((uint4*)out)[q];
    }
}

// -------------------- prep: weights -> pre-swizzled fp16 tiles -------------
__global__ void wprep_kernel(const float* __restrict__ src,
                             unsigned char* __restrict__ dst,
                             int KB, int ldb) {
    int tn = blockIdx.x, kb = blockIdx.y, e = blockIdx.z;
    int NTN = gridDim.x;
    int t = threadIdx.x;
    int n = t & 127;
    int half = t >> 7;
    const float* s = src + (size_t)e * (size_t)(KB * 64) * ldb
                   + (size_t)(kb * 64 + half * 32) * ldb + (size_t)tn * 128 + n;
    unsigned char* d = dst + ((size_t)(e * NTN + tn) * KB + kb) * 16384;

    float v[32];
#pragma unroll
    for (int k = 0; k < 32; ++k)
        v[k] = s[(size_t)k * ldb];
    unsigned out[16];
#pragma unroll
    for (int p = 0; p < 16; ++p) {
        __half2 hh = __floats2half2_rn(v[2 * p], v[2 * p + 1]);
        out[p] = *(unsigned*)&hh;
    }
#pragma unroll
    for (int q = 0; q < 4; ++q) {
        unsigned so = sw128((unsigned)(n * 128 + half * 64 + q * 16));
        *(uint4*)(d + so) = ((uint4*)out)[q];
    }
}

// -------------------- grouped GEMM (256 rows x 256 cols per CTA) -----------
// MODE 0: hmid tiles = fp16(gelu(xt @ win_tiles)),  K=HDIM  (KT64=32,  NT_N=32)
// MODE 1: ypart = roww * (hmid tiles @ wout_tiles), K=IDIM  (KT64=128, NT_N=8)
// 1D grid with 16x8 supertile swizzle: each ~wave covers 16 m-tiles x 8
// n-pairs so both A and B tiles are L2-reused within the wave.
template <int MODE, int KT64>
__global__ __launch_bounds__(256, 1)
void gemm_tc(const float* __restrict__ Xraw, const float* __restrict__ Braw) {
    const int NT_N = (MODE == 0) ? 32 : 8;   // n-pair tiles
    // supertile decode: 128 CTAs per supertile (16 m x 8 n)
    const int within = blockIdx.x & 127;
    const int st     = blockIdx.x >> 7;
    const int NSN    = NT_N / 8;             // n-supercols
    const int sn     = st % NSN;
    const int sm     = st / NSN;
    const int mslot  = sm * 16 + (within & 15);   // 0..255 = e*32+tm
    const int tnp    = sn * 8 + (within >> 4);
    const int e      = mslot >> 5;
    const int tm     = mslot & 31;

    const int cnt = g_count[e];
    if (tm * 256 >= cnt) return;
    const int row0 = g_off[e] + tm * 256;    // 256-aligned
    const int ldb  = (MODE == 0) ? IDIM : HDIM;
    const int NTN  = (MODE == 0) ? 64 : 16;  // 128-col weight tiles
    const int mt0  = row0 >> 7;

    extern __shared__ char smem[];
    const int tid  = threadIdx.x;
    const int wid  = tid >> 5;
    const int lane = tid & 31;

    const unsigned char* Abase =
        (MODE == 0 ? g_xt : g_hmid_t) + (size_t)mt0 * KT64 * 16384;
    const unsigned char* Bbase =
        (MODE == 0 ? g_win_t : g_wout_t) + (size_t)(e * NTN + tnp * 2) * KT64 * 16384;

#if TC_ON
    uint32_t smem_base = smem_to_u32(smem);
    if (wid == 0) TCGEN05_ALLOC(smem_base, 512);
    if (tid == 0) {
#pragma unroll
        for (int s = 0; s < NSTG; ++s) {
            MBARRIER_INIT(smem_base + FULLB(s), 1);    // expect_tx only
            MBARRIER_INIT(smem_base + EMPTYB(s), 1);   // MMA commit
        }
    }
    __syncthreads();
    uint32_t tmem;
    asm volatile("ld.shared.b32 %0, [%1];" : "=r"(tmem) : "r"(smem_base));

    if (wid == 4) {
        // ---------------- producer: 4 bulk copies per k-block --------------
        if (elect_one_pred()) {
            const unsigned char* a0p = Abase;                           // mt0
            const unsigned char* a1p = Abase + (size_t)KT64 * 16384;    // mt0+1
            const unsigned char* b0p = Bbase;                           // tn0
            const unsigned char* b1p = Bbase + (size_t)KT64 * 16384;    // tn1
            for (int kb = 0; kb < KT64; ++kb) {
                int s = kb % NSTG, w = kb / NSTG;
                MBARRIER_WAIT_PARITY(smem_base + EMPTYB(s), (w + 1) & 1);
                MBARRIER_EXPECT_TX(smem_base + FULLB(s), 65536);
                uint32_t stg = smem_base + SM_STG(s);
                size_t o = (size_t)kb * 16384;
                CP_ASYNC_BULK(stg,         a0p + o, 16384, smem_base + FULLB(s));
                CP_ASYNC_BULK(stg + 16384, a1p + o, 16384, smem_base + FULLB(s));
                CP_ASYNC_BULK(stg + 32768, b0p + o, 16384, smem_base + FULLB(s));
                CP_ASYNC_BULK(stg + 49152, b1p + o, 16384, smem_base + FULLB(s));
            }
        }
    } else if (wid == 5) {
        // ---------------- MMA issuer: 4 quadrants x 4 K-steps --------------
        if (elect_one_pred()) {
            for (int kb = 0; kb < KT64; ++kb) {
                int s = kb % NSTG, w = kb / NSTG;
                MBARRIER_WAIT_PARITY(smem_base + FULLB(s), w & 1);
                asm volatile("fence.proxy.async.shared::cta;" ::: "memory");
                uint64_t S  = MAKE_SMEM_DESC(smem_base + SM_STG(s));
                uint64_t A0 = S, A1 = S + 1024, B0 = S + 2048, B1 = S + 3072;
                bool first = (kb == 0);
#pragma unroll
                for (int st2 = 0; st2 < 4; ++st2)
                    mma_ss(tmem, A0 + st2 * 2, B0 + st2 * 2, GEMM_IDESC, !(first && st2 == 0));
#pragma unroll
                for (int st2 = 0; st2 < 4; ++st2)
                    mma_ss(tmem + 128, A1 + st2 * 2, B0 + st2 * 2, GEMM_IDESC, !(first && st2 == 0));
#pragma unroll
                for (int st2 = 0; st2 < 4; ++st2)
                    mma_ss(tmem + 256, A0 + st2 * 2, B1 + st2 * 2, GEMM_IDESC, !(first && st2 == 0));
#pragma unroll
                for (int st2 = 0; st2 < 4; ++st2)
                    mma_ss(tmem + 384, A1 + st2 * 2, B1 + st2 * 2, GEMM_IDESC, !(first && st2 == 0));
                TCGEN05_COMMIT(smem_base + EMPTYB(s));
            }
        }
    }
    __syncthreads();

    // ---------------- epilogue: warps 0-3, 4 quadrants ---------------------
    if (wid < 4) {
        MBARRIER_WAIT_PARITY(smem_base + EMPTYB((KT64 - 1) % NSTG),
                             ((KT64 - 1) / NSTG) & 1);
        TCGEN05_FENCE_AFTER();
#pragma unroll
        for (int np = 0; np < 2; ++np) {
#pragma unroll
            for (int sub = 0; sub < 2; ++sub) {
                int rloc = wid * 32 + lane;            // row within 128-tile
                int m = sub * 128 + rloc;
                int grow = row0 + m;
                bool valid = (tm * 256 + m) < cnt;
                float wscale = 1.f;
                if (MODE == 1) wscale = valid ? g_roww[grow] : 0.f;
#pragma unroll
                for (int nb = 0; nb < 4; ++nb) {
                    uint32_t dr[32];
                    TCGEN05_LD_32X32B_X32(dr, tmem + np * 256 + sub * 128 + nb * 32);
                    TCGEN05_WAIT_LD();
                    float f[32];
#pragma unroll
                    for (int j = 0; j < 32; ++j) f[j] = __uint_as_float(dr[j]);
                    if (MODE == 0) {
#pragma unroll
                        for (int j = 0; j < 32; ++j) {
                            float t = f[j];
                            f[j] = 0.5f * t * (1.0f + erff(t * 0.7071067811865476f));
                        }
                        unsigned oh[16];
#pragma unroll
                        for (int p = 0; p < 16; ++p) {
                            __half2 hh = __floats2half2_rn(f[2 * p], f[2 * p + 1]);
                            oh[p] = *(unsigned*)&hh;
                        }
                        int c0 = (tnp * 2 + np) * 128 + nb * 32;   // global col
                        int kbi = c0 >> 6, hf = (c0 >> 5) & 1;
                        unsigned char* d = g_hmid_t
                            + ((size_t)(mt0 + sub) * 128 + kbi) * 16384;
#pragma unroll
                        for (int q = 0; q < 4; ++q) {
                            unsigned so = sw128((unsigned)(rloc * 128 + hf * 64 + q * 16));
                            *(uint4*)(d + so) = ((uint4*)oh)[q];
                        }
                    } else if (valid) {
#pragma unroll
                        for (int j = 0; j < 32; ++j) f[j] *= wscale;
                        float* dst = g_ypart + (size_t)grow * HDIM
                                   + (size_t)(tnp * 2 + np) * 128 + nb * 32;
#pragma unroll
                        for (int q = 0; q < 8; ++q)
                            *(float4*)(dst + 4 * q) =
                                make_float4(f[4 * q], f[4 * q + 1], f[4 * q + 2], f[4 * q + 3]);
                    }
                }
            }
        }
        TCGEN05_FENCE_BEFORE();
    }
    __syncthreads();
    if (wid == 0) {
        TCGEN05_RELINQUISH();
        TCGEN05_DEALLOC(tmem, 512);
    }

#else
    // ================= FFMA2 SIMT fallback (compiles on plain sm_103) ======
    (void)lane; (void)wid; (void)Abase; (void)Bbase;
    const int lda = (MODE == 0) ? HDIM : IDIM;
    const int KT16 = KT64 * 4;
    float* As = (float*)smem;
    float* Bs = As + 2 * 16 * 128;
    __half* hmidL = (__half*)g_hmid_t;

    for (int sub = 0; sub < 2; ++sub) {
        for (int np = 0; np < 2; ++np) {
            int mbase = tm * 256 + sub * 128;
            if (mbase >= cnt) break;
            int rowb = row0 + sub * 128;
            int tn = tnp * 2 + np;
            __syncthreads();

            const int am  = tid & 127;
            const int akq = (tid >> 7) << 3;
            const bool avalid = (mbase + am) < cnt;
            int arow_idx = avalid ? (rowb + am) : row0;
            const float* AxRow = Xraw + (size_t)g_rowtok[arow_idx] * HDIM + akq;
            const __half* AhRow = hmidL + (size_t)arow_idx * lda + akq;

            const float* Bb = Braw + (size_t)e * (size_t)KT64 * 64 * ldb + (size_t)tn * 128;
            const int bk = tid >> 4;
            const int bn = (tid & 15) << 3;
            const float* Bp = Bb + (size_t)bk * ldb + bn;
            const int m0 = (tid >> 4) << 3;
            const int n0 = (tid & 15) << 3;

            unsigned long long acc[8][4];
#pragma unroll
            for (int i = 0; i < 8; ++i)
#pragma unroll
                for (int j = 0; j < 4; ++j) acc[i][j] = 0ull;

            auto loadA8 = [&](int k0, float* out8) {
                if (MODE == 0) {
                    float4 a = *(const float4*)(AxRow + k0);
                    float4 b = *(const float4*)(AxRow + k0 + 4);
                    out8[0] = a.x; out8[1] = a.y; out8[2] = a.z; out8[3] = a.w;
                    out8[4] = b.x; out8[5] = b.y; out8[6] = b.z; out8[7] = b.w;
                } else {
                    uint4 h = *(const uint4*)(AhRow + k0);
                    const __half2* hp = (const __half2*)&h;
#pragma unroll
                    for (int p = 0; p < 4; ++p) {
                        float2 hf = __half22float2(hp[p]);
                        out8[2 * p] = hf.x;
                        out8[2 * p + 1] = hf.y;
                    }
                }
            };

            {
                float a8[8];
                loadA8(0, a8);
#pragma unroll
                for (int q = 0; q < 8; ++q) As[(akq + q) * 128 + am] = a8[q];
                *(float4*)&Bs[bk * 128 + bn]     = *(const float4*)(Bp);
                *(float4*)&Bs[bk * 128 + bn + 4] = *(const float4*)(Bp + 4);
            }
            __syncthreads();

            int buf = 0;
            for (int kt = 0; kt < KT16; ++kt) {
                float na8[8]; float4 nb0, nb1;
                if (kt + 1 < KT16) {
                    int k0 = (kt + 1) * 16;
                    loadA8(k0, na8);
                    nb0 = *(const float4*)(Bp + (size_t)k0 * ldb);
                    nb1 = *(const float4*)(Bp + (size_t)k0 * ldb + 4);
                }
                const float* Ab = As + buf * 16 * 128;
                const float* Bbs = Bs + buf * 16 * 128;
#pragma unroll
                for (int kk = 0; kk < 16; ++kk) {
                    float a8[8];
                    *(float4*)&a8[0] = *(const float4*)&Ab[kk * 128 + m0];
                    *(float4*)&a8[4] = *(const float4*)&Ab[kk * 128 + m0 + 4];
                    ulonglong2 bb0 = *(const ulonglong2*)&Bbs[kk * 128 + n0];
                    ulonglong2 bb1 = *(const ulonglong2*)&Bbs[kk * 128 + n0 + 4];
                    unsigned long long b2[4] = {bb0.x, bb0.y, bb1.x, bb1.y};
#pragma unroll
                    for (int i = 0; i < 8; ++i) {
                        unsigned long long a2 = pack2(a8[i], a8[i]);
#pragma unroll
                        for (int j = 0; j < 4; ++j) ffma2(acc[i][j], a2, b2[j]);
                    }
                }
                if (kt + 1 < KT16) {
                    int nb2 = buf ^ 1;
                    float* An = As + nb2 * 16 * 128;
#pragma unroll
                    for (int q = 0; q < 8; ++q) An[(akq + q) * 128 + am] = na8[q];
                    float* Bn = Bs + nb2 * 16 * 128;
                    *(float4*)&Bn[bk * 128 + bn]     = nb0;
                    *(float4*)&Bn[bk * 128 + bn + 4] = nb1;
                    __syncthreads();
                    buf = nb2;
                }
            }

#pragma unroll
            for (int i = 0; i < 8; ++i) {
                int r = mbase + m0 + i;
                if (r < cnt) {
                    int grow = rowb + m0 + i;
                    float v[8];
#pragma unroll
                    for (int j = 0; j < 4; ++j) unpack2(acc[i][j], v[2 * j], v[2 * j + 1]);
                    if (MODE == 0) {
#pragma unroll
                        for (int k = 0; k < 8; ++k) {
                            float t = v[k];
                            v[k] = 0.5f * t * (1.0f + erff(t * 0.7071067811865476f));
                        }
                        size_t off = (size_t)grow * IDIM + (size_t)tn * 128 + n0;
#pragma unroll
                        for (int p = 0; p < 4; ++p) {
                            __half2 hh = __floats2half2_rn(v[2 * p], v[2 * p + 1]);
                            *(unsigned*)(hmidL + off + 2 * p) = *(unsigned*)&hh;
                        }
                    } else {
                        float w = g_roww[grow];
#pragma unroll
                        for (int k = 0; k < 8; ++k) v[k] *= w;
                        float* dst = g_ypart + (size_t)grow * HDIM + (size_t)tn * 128 + n0;
                        *(float4*)(dst)     = make_float4(v[0], v[1], v[2], v[3]);
                        *(float4*)(dst + 4) = make_float4(v[4], v[5], v[6], v[7]);
                    }
                }
            }
            __syncthreads();
        }
    }
#endif  // TC_ON
}

// -------------------- combine ----------------------------------------------
__global__ void combine_kernel(const float* __restrict__ bias,
                               float* __restrict__ out) {
    int idx = blockIdx.x * blockDim.x + threadIdx.x;
    if (idx >= NTOK * (HDIM / 4)) return;
    int t  = idx >> 9;
    int c4 = (idx & 511) << 2;
    int p0 = g_pairpos[t * 2];
    int p1 = g_pairpos[t * 2 + 1];
    float4 bv = *(const float4*)(bias + c4);
    float4 y0 = *(const float4*)(g_ypart + (size_t)p0 * HDIM + c4);
    float4 y1 = *(const float4*)(g_ypart + (size_t)p1 * HDIM + c4);
    float4 o;
    o.x = bv.x + y0.x + y1.x;
    o.y = bv.y + y0.y + y1.y;
    o.z = bv.z + y0.z + y1.z;
    o.w = bv.w + y0.w + y1.w;
    *(float4*)(out + (size_t)t * HDIM + c4) = o;
}

// ---------------------------------------------------------------------------
extern "C" void kernel_launch(void* const* d_in, const int* in_sizes, int n_in,
                              void* d_out, int out_size) {
    const float* x     = (const float*)d_in[0];
    const float* gw    = (const float*)d_in[1];
    const float* w_in  = (const float*)d_in[2];
    const float* w_out = (const float*)d_in[3];
    const float* bias  = (const float*)d_in[4];
    (void)in_sizes; (void)n_in; (void)out_size;

    float* out    = (float*)d_out;
    float* logits = out + (size_t)NTOK * HDIM;

    unsigned char* win_t;
    unsigned char* wout_t;
    cudaGetSymbolAddress((void**)&win_t, g_win_t);
    cudaGetSymbolAddress((void**)&wout_t, g_wout_t);

    cudaFuncSetAttribute(gemm_tc<0, HDIM / 64>,
                         cudaFuncAttributeMaxDynamicSharedMemorySize, SMEM_BYTES);
    cudaFuncSetAttribute(gemm_tc<1, IDIM / 64>,
                         cudaFuncAttributeMaxDynamicSharedMemorySize, SMEM_BYTES);

    // Serial launch order (R14) — the R15 stream fork contended with the
    // 1-CTA/SM GEMMs and regressed; keep everything on one stream.
    router_kernel<<<NTOK / 8, 256>>>(x, gw, logits);
    assign_fused_kernel<<<1, 1024>>>();
    xtile_kernel<<<dim3(MT_TOT, 32), 256>>>(x);
    wprep_kernel<<<dim3(64, 32, NEXP), 256>>>(w_in, win_t, 32, IDIM);
    wprep_kernel<<<dim3(16, 128, NEXP), 256>>>(w_out, wout_t, 128, HDIM);
    // 1D swizzled grids: GEMM1 = 256 mslots x 32 npairs = 8192 CTAs,
    // GEMM2 = 256 mslots x 8 npairs = 2048 CTAs.
    gemm_tc<0, HDIM / 64><<<8192, 256, SMEM_BYTES>>>(x, w_in);
    gemm_tc<1, IDIM / 64><<<2048, 256, SMEM_BYTES>>>(x, w_out);
    combine_kernel<<<(NTOK * (HDIM / 4)) / 256, 256>>>(bias, out);
}